// round 1
// baseline (speedup 1.0000x reference)
#include <cuda_runtime.h>
#include <cuda_bf16.h>

// Problem constants (fixed by the dataset)
#define T_TOK 16384
#define DDIM  1024
#define NEXP  8

// Per-expert compaction lists (scratch via __device__ globals per harness rules)
__device__ int   g_count[NEXP];
__device__ int   g_tok [NEXP][T_TOK];
__device__ float g_gate[NEXP][T_TOK];

// ---------------------------------------------------------------------------
// Kernel 0: zero output + expert counters
// ---------------------------------------------------------------------------
__global__ void zero_kernel(float* __restrict__ out) {
    int i = blockIdx.x * blockDim.x + threadIdx.x;
    int n4 = (T_TOK * DDIM) / 4;
    if (i < n4) reinterpret_cast<float4*>(out)[i] = make_float4(0.f, 0.f, 0.f, 0.f);
    if (blockIdx.x == 0 && threadIdx.x < NEXP) g_count[threadIdx.x] = 0;
}

// ---------------------------------------------------------------------------
// Kernel 1: gating. fp32 logits, exact top-2 (lowest-index tie-break like
// jax.lax.top_k), softmax over the 2, compact tokens into per-expert lists.
// One warp per token, Wg staged in smem.
// ---------------------------------------------------------------------------
__global__ void gate_kernel(const float* __restrict__ x,
                            const float* __restrict__ Wg,
                            const float* __restrict__ bg) {
    __shared__ float sWg[NEXP * DDIM];
    int tid = threadIdx.x;                       // 256 threads
    for (int i = tid; i < NEXP * DDIM; i += 256) sWg[i] = Wg[i];
    __syncthreads();

    int warp = tid >> 5, lane = tid & 31;
    int t = blockIdx.x * 8 + warp;
    if (t >= T_TOK) return;

    const float4* xr = reinterpret_cast<const float4*>(x + (size_t)t * DDIM);
    float acc[NEXP];
#pragma unroll
    for (int e = 0; e < NEXP; e++) acc[e] = 0.f;

#pragma unroll
    for (int j = 0; j < 8; j++) {                // 8 float4 per lane covers D=1024
        float4 xv = xr[j * 32 + lane];
#pragma unroll
        for (int e = 0; e < NEXP; e++) {
            float4 wv = reinterpret_cast<const float4*>(sWg + e * DDIM)[j * 32 + lane];
            acc[e] += xv.x * wv.x + xv.y * wv.y + xv.z * wv.z + xv.w * wv.w;
        }
    }
#pragma unroll
    for (int off = 16; off > 0; off >>= 1)
#pragma unroll
        for (int e = 0; e < NEXP; e++)
            acc[e] += __shfl_xor_sync(0xFFFFFFFFu, acc[e], off);

    if (lane == 0) {
        float l[NEXP];
#pragma unroll
        for (int e = 0; e < NEXP; e++) l[e] = acc[e] + bg[e];
        int i0 = 0;
#pragma unroll
        for (int e = 1; e < NEXP; e++) if (l[e] > l[i0]) i0 = e;
        int i1 = -1;
#pragma unroll
        for (int e = 0; e < NEXP; e++) {
            if (e == i0) continue;
            if (i1 < 0 || l[e] > l[i1]) i1 = e;
        }
        float m  = fmaxf(l[i0], l[i1]);
        float e0 = __expf(l[i0] - m);
        float e1 = __expf(l[i1] - m);
        float inv = 1.f / (e0 + e1);
        float g0 = e0 * inv, g1 = e1 * inv;

        int p0 = atomicAdd(&g_count[i0], 1);
        g_tok[i0][p0] = t; g_gate[i0][p0] = g0;
        int p1 = atomicAdd(&g_count[i1], 1);
        g_tok[i1][p1] = t; g_gate[i1][p1] = g1;
    }
}

// ---------------------------------------------------------------------------
// Kernel 2: per-expert gathered SGEMM, 128x128 tile, BK=8, 256 threads,
// 8x8 micro-tile per thread. Epilogue: out[tok] += g * (acc + be[e]).
// Grid: (n_tiles=8, m_tiles=128, experts=8); empty tiles early-exit.
// ---------------------------------------------------------------------------
__global__ void __launch_bounds__(256, 2)
expert_gemm_kernel(const float* __restrict__ x,
                   const float* __restrict__ We,
                   const float* __restrict__ be,
                   float* __restrict__ out) {
    const int e = blockIdx.z;
    const int cnt = g_count[e];
    const int m0 = blockIdx.y * 128;
    if (m0 >= cnt) return;
    const int n0 = blockIdx.x * 128;

    __shared__ float Xs[8][132];
    __shared__ float Ws[8][132];

    const int tid = threadIdx.x;
    const int lm = tid >> 1;               // 0..127: which tile row I stage
    const int lk = (tid & 1) * 4;          // k sub-offset (0 or 4)

    // Gathered X row for staging
    int tok_ld = -1;
    if (m0 + lm < cnt) tok_ld = g_tok[e][m0 + lm];
    const float* xrow = (tok_ld >= 0) ? (x + (size_t)tok_ld * DDIM) : x;
    const float* wrow = We + (size_t)e * DDIM * DDIM + (size_t)(n0 + lm) * DDIM;

    float acc[8][8];
#pragma unroll
    for (int i = 0; i < 8; i++)
#pragma unroll
        for (int j = 0; j < 8; j++) acc[i][j] = 0.f;

    const int tr = (tid >> 4) * 8;         // my 8 output rows within tile
    const int tc = (tid & 15) * 8;         // my 8 output cols within tile

    // software pipeline: preload k-tile 0
    float4 av = make_float4(0.f, 0.f, 0.f, 0.f);
    if (tok_ld >= 0) av = *reinterpret_cast<const float4*>(xrow + lk);
    float4 bv = *reinterpret_cast<const float4*>(wrow + lk);

    for (int k0 = 0; k0 < DDIM; k0 += 8) {
        __syncthreads();
        Xs[lk + 0][lm] = av.x; Xs[lk + 1][lm] = av.y;
        Xs[lk + 2][lm] = av.z; Xs[lk + 3][lm] = av.w;
        Ws[lk + 0][lm] = bv.x; Ws[lk + 1][lm] = bv.y;
        Ws[lk + 2][lm] = bv.z; Ws[lk + 3][lm] = bv.w;
        __syncthreads();

        if (k0 + 8 < DDIM) {
            if (tok_ld >= 0) av = *reinterpret_cast<const float4*>(xrow + k0 + 8 + lk);
            bv = *reinterpret_cast<const float4*>(wrow + k0 + 8 + lk);
        }

#pragma unroll
        for (int k = 0; k < 8; k++) {
            float a[8], b[8];
            float4 a0 = *reinterpret_cast<const float4*>(&Xs[k][tr]);
            float4 a1 = *reinterpret_cast<const float4*>(&Xs[k][tr + 4]);
            float4 b0 = *reinterpret_cast<const float4*>(&Ws[k][tc]);
            float4 b1 = *reinterpret_cast<const float4*>(&Ws[k][tc + 4]);
            a[0]=a0.x; a[1]=a0.y; a[2]=a0.z; a[3]=a0.w;
            a[4]=a1.x; a[5]=a1.y; a[6]=a1.z; a[7]=a1.w;
            b[0]=b0.x; b[1]=b0.y; b[2]=b0.z; b[3]=b0.w;
            b[4]=b1.x; b[5]=b1.y; b[6]=b1.z; b[7]=b1.w;
#pragma unroll
            for (int i = 0; i < 8; i++)
#pragma unroll
                for (int j = 0; j < 8; j++)
                    acc[i][j] = fmaf(a[i], b[j], acc[i][j]);
        }
    }

    // Epilogue: out[tok] += g * (acc + be)
    const float* berow = be + e * DDIM + n0 + tc;
#pragma unroll
    for (int i = 0; i < 8; i++) {
        int m = m0 + tr + i;
        if (m >= cnt) continue;
        int tok = g_tok[e][m];
        float g = g_gate[e][m];
        float* orow = out + (size_t)tok * DDIM + n0 + tc;
#pragma unroll
        for (int j = 0; j < 8; j++)
            atomicAdd(&orow[j], g * (acc[i][j] + berow[j]));
    }
}

// ---------------------------------------------------------------------------
extern "C" void kernel_launch(void* const* d_in, const int* in_sizes, int n_in,
                              void* d_out, int out_size) {
    const float* x  = (const float*)d_in[0];   // [16384, 1024]
    const float* Wg = (const float*)d_in[1];   // [8, 1024]
    const float* bg = (const float*)d_in[2];   // [8]
    const float* We = (const float*)d_in[3];   // [8, 1024, 1024]
    const float* be = (const float*)d_in[4];   // [8, 1024]
    float* out = (float*)d_out;                // [16384, 1024]

    int n4 = (T_TOK * DDIM) / 4;
    zero_kernel<<<(n4 + 255) / 256, 256>>>(out);

    gate_kernel<<<T_TOK / 8, 256>>>(x, Wg, bg);

    dim3 grid(DDIM / 128, T_TOK / 128, NEXP);  // (n-tiles, m-tiles, experts)
    expert_gemm_kernel<<<grid, 256>>>(x, We, be, out);
}